// round 5
// baseline (speedup 1.0000x reference)
#include <cuda_runtime.h>
#include <cuda_bf16.h>
#include <stdint.h>
#include <math.h>

// ---------------------------------------------------------------- scratch
__device__ float g_logits[8 * 8 * 32 * 32];   // [b][n][h][w] raw logits
__device__ float g_vsum[8 * 8 * 32 * 32];     // [b][n][x][y]
__device__ float g_wvsum[8 * 512];
__device__ __nv_bfloat16 g_xhi[8192 * 512];
__device__ __nv_bfloat16 g_xlo[8192 * 512];
__device__ __nv_bfloat16 g_wqhi[512 * 512];
__device__ __nv_bfloat16 g_wqlo[512 * 512];
__device__ __nv_bfloat16 g_wkhi[512 * 512];
__device__ __nv_bfloat16 g_wklo[512 * 512];

// ---------------------------------------------------------------- helpers
__device__ __forceinline__ uint32_t smem_u32(const void* p) {
    uint32_t a;
    asm("{ .reg .u64 t; cvta.to.shared.u64 t, %1; cvt.u32.u64 %0, t; }" : "=r"(a) : "l"(p));
    return a;
}
__device__ __forceinline__ void ldsm4(uint32_t* r, uint32_t addr) {
    asm volatile("ldmatrix.sync.aligned.m8n8.x4.shared.b16 {%0,%1,%2,%3}, [%4];"
                 : "=r"(r[0]), "=r"(r[1]), "=r"(r[2]), "=r"(r[3]) : "r"(addr));
}
__device__ __forceinline__ void mma16816(float* d, const uint32_t* a, const uint32_t* b) {
    asm volatile(
        "mma.sync.aligned.m16n8k16.row.col.f32.bf16.bf16.f32 "
        "{%0,%1,%2,%3}, {%4,%5,%6,%7}, {%8,%9}, {%0,%1,%2,%3};"
        : "+f"(d[0]), "+f"(d[1]), "+f"(d[2]), "+f"(d[3])
        : "r"(a[0]), "r"(a[1]), "r"(a[2]), "r"(a[3]), "r"(b[0]), "r"(b[1]));
}
__device__ __forceinline__ void cp_async16(uint32_t dst, const void* src) {
    asm volatile("cp.async.cg.shared.global [%0], [%1], 16;"
                 :: "r"(dst), "l"(__cvta_generic_to_global(src)) : "memory");
}
__device__ __forceinline__ void cp_commit_wait() {
    asm volatile("cp.async.commit_group;\ncp.async.wait_group 0;" ::: "memory");
}

// ---------------------------------------------------------------- kernel: hi/lo split
__global__ void split_kernel(const float* __restrict__ src,
                             __nv_bfloat16* __restrict__ hi,
                             __nv_bfloat16* __restrict__ lo, int n4) {
    int i = blockIdx.x * blockDim.x + threadIdx.x;
    if (i >= n4) return;
    float4 v = ((const float4*)src)[i];
    __nv_bfloat16 h0 = __float2bfloat16(v.x), h1 = __float2bfloat16(v.y);
    __nv_bfloat16 h2 = __float2bfloat16(v.z), h3 = __float2bfloat16(v.w);
    __nv_bfloat16 l0 = __float2bfloat16(v.x - __bfloat162float(h0));
    __nv_bfloat16 l1 = __float2bfloat16(v.y - __bfloat162float(h1));
    __nv_bfloat16 l2 = __float2bfloat16(v.z - __bfloat162float(h2));
    __nv_bfloat16 l3 = __float2bfloat16(v.w - __bfloat162float(h3));
    ((ushort4*)hi)[i] = make_ushort4(__bfloat16_as_ushort(h0), __bfloat16_as_ushort(h1),
                                     __bfloat16_as_ushort(h2), __bfloat16_as_ushort(h3));
    ((ushort4*)lo)[i] = make_ushort4(__bfloat16_as_ushort(l0), __bfloat16_as_ushort(l1),
                                     __bfloat16_as_ushort(l2), __bfloat16_as_ushort(l3));
}

// ---------------------------------------------------------------- kernel: wvsum
__global__ void wvsum_kernel(const float* __restrict__ wv) {
    int n = blockIdx.x, c = threadIdx.x;
    const float* base = wv + (size_t)(n * 64) * 512 + c;
    float s = 0.f;
#pragma unroll 8
    for (int d = 0; d < 64; ++d) s += base[d * 512];
    g_wvsum[n * 512 + c] = s;
}

// ---------------------------------------------------------------- kernel: vsum (fp32)
__global__ void vsum_kernel(const float* __restrict__ x) {
    int p = blockIdx.x * 8 + (threadIdx.x >> 5);
    int lane = threadIdx.x & 31;
    const float4* xr = (const float4*)(x + (size_t)p * 512);
    float4 xv[4];
#pragma unroll
    for (int t = 0; t < 4; ++t) xv[t] = xr[lane * 4 + t];
    float acc[8];
#pragma unroll
    for (int n = 0; n < 8; ++n) {
        const float4* wr = (const float4*)(g_wvsum + n * 512);
        float s = 0.f;
#pragma unroll
        for (int t = 0; t < 4; ++t) {
            float4 w = wr[lane * 4 + t];
            s = fmaf(xv[t].x, w.x, s); s = fmaf(xv[t].y, w.y, s);
            s = fmaf(xv[t].z, w.z, s); s = fmaf(xv[t].w, w.w, s);
        }
#pragma unroll
        for (int o = 16; o > 0; o >>= 1) s += __shfl_xor_sync(0xffffffffu, s, o);
        acc[n] = s;
    }
    if (lane < 8) {
        float v = acc[0];
#pragma unroll
        for (int n = 1; n < 8; ++n) if (lane == n) v = acc[n];
        int b = p >> 10, pos = p & 1023;
        g_vsum[(b * 8 + lane) * 1024 + pos] = v;
    }
}

// ---------------------------------------------------------------- kernel: QK via mma.sync
// block = (128-pixel tile) x (head). 256 threads / 8 warps, 16 rows per warp.
// smem bf16 tiles, row stride 144 B (72 elems) for conflict-free ldmatrix.
static constexpr int RS   = 144;
static constexpr int XH_O = 0;              // X hi  (128 x 72)
static constexpr int XL_O = 18432;          // X lo
static constexpr int QH_O = 36864;          // Wq hi (64 x 72)
static constexpr int QL_O = 46080;
static constexpr int KH_O = 55296;
static constexpr int KL_O = 64512;
static constexpr int SM_TOTAL = 73728;

__global__ void __launch_bounds__(256, 2)
qk_kernel() {
    extern __shared__ char smem[];
    const uint32_t sb = smem_u32(smem);
    const int tid  = threadIdx.x;
    const int lane = tid & 31;
    const int wid  = tid >> 5;
    const int tile = blockIdx.x;      // 0..63
    const int head = blockIdx.y;      // 0..7
    const int pix0 = tile * 128;

    const uint32_t a_off = sb + (uint32_t)(wid * 16 + (lane & 15)) * RS + ((lane >> 4) << 4);
    const uint32_t b_row = (lane & 7) + ((lane >> 4) << 3);
    const uint32_t b_off = sb + b_row * RS + (((lane >> 3) & 1) << 4);

    float accQ[8][4], accK[8][4];
#pragma unroll
    for (int i = 0; i < 8; ++i)
#pragma unroll
        for (int j = 0; j < 4; ++j) { accQ[i][j] = 0.f; accK[i][j] = 0.f; }

    // precomputed per-thread copy indices
    const int xr = tid >> 3, xc8 = tid & 7;          // X: row tid/8, 16B-chunk tid%8 (x2 arrays, 4 row-groups)
    for (int ch = 0; ch < 8; ++ch) {
        const int c0 = ch * 64;
        // X hi+lo: 128 rows x 8 chunks x 2 arrays = 2048 cp; 8 per thread
#pragma unroll
        for (int g = 0; g < 4; ++g) {
            int r = xr + g * 32;
            uint32_t so = (uint32_t)r * RS + xc8 * 16;
            const size_t gg = (size_t)(pix0 + r) * 512 + c0 + xc8 * 8;
            cp_async16(sb + XH_O + so, g_xhi + gg);
            cp_async16(sb + XL_O + so, g_xlo + gg);
        }
        // W: 64 rows x 8 chunks x 4 arrays = 2048 cp; 8 per thread
        {
            int r = (tid >> 3) & 63;                 // 0..63 (tid 0..511 wraps at 256: use two halves)
            int half = tid >> 8;                     // always 0 for 256 threads
            (void)half;
            uint32_t so = (uint32_t)r * RS + xc8 * 16;
            const size_t gg = (size_t)(head * 64 + r) * 512 + c0 + xc8 * 8;
            if (tid < 512) {                          // all threads
                // each thread does all 4 arrays for its (r,c8) pair: covers 64x8 per array... 
            }
            cp_async16(sb + QH_O + so, g_wqhi + gg);
            cp_async16(sb + QL_O + so, g_wqlo + gg);
            cp_async16(sb + KH_O + so, g_wkhi + gg);
            cp_async16(sb + KL_O + so, g_wklo + gg);
            // tid 0..255 covers rows 0..31; second half rows 32..63:
            int r2 = r + 32;
            uint32_t so2 = (uint32_t)r2 * RS + xc8 * 16;
            const size_t gg2 = (size_t)(head * 64 + r2) * 512 + c0 + xc8 * 8;
            cp_async16(sb + QH_O + so2, g_wqhi + gg2);
            cp_async16(sb + QL_O + so2, g_wqlo + gg2);
            cp_async16(sb + KH_O + so2, g_wkhi + gg2);
            cp_async16(sb + KL_O + so2, g_wklo + gg2);
        }
        cp_commit_wait();
        __syncthreads();

#pragma unroll
        for (int ks = 0; ks < 4; ++ks) {
            const uint32_t ko = ks * 32;
            uint32_t ah[4], al[4];
            ldsm4(ah, a_off + XH_O + ko);
            ldsm4(al, a_off + XL_O + ko);
#pragma unroll
            for (int np = 0; np < 4; ++np) {
                const uint32_t off = b_off + np * (16 * RS) + ko;
                uint32_t bh[4], bl[4];
                ldsm4(bh, off + QH_O);
                ldsm4(bl, off + QL_O);
                mma16816(accQ[np * 2],     ah, bh);
                mma16816(accQ[np * 2],     ah, bl);
                mma16816(accQ[np * 2],     al, bh);
                mma16816(accQ[np * 2 + 1], ah, bh + 2);
                mma16816(accQ[np * 2 + 1], ah, bl + 2);
                mma16816(accQ[np * 2 + 1], al, bh + 2);
                ldsm4(bh, off + KH_O);
                ldsm4(bl, off + KL_O);
                mma16816(accK[np * 2],     ah, bh);
                mma16816(accK[np * 2],     ah, bl);
                mma16816(accK[np * 2],     al, bh);
                mma16816(accK[np * 2 + 1], ah, bh + 2);
                mma16816(accK[np * 2 + 1], ah, bl + 2);
                mma16816(accK[np * 2 + 1], al, bh + 2);
            }
        }
        __syncthreads();
    }

    // epilogue: per-pixel dot over the 64 j's
    float plo = 0.f, phi = 0.f;
#pragma unroll
    for (int nt = 0; nt < 8; ++nt) {
        plo = fmaf(accQ[nt][0], accK[nt][0], plo);
        plo = fmaf(accQ[nt][1], accK[nt][1], plo);
        phi = fmaf(accQ[nt][2], accK[nt][2], phi);
        phi = fmaf(accQ[nt][3], accK[nt][3], phi);
    }
    plo += __shfl_xor_sync(0xffffffffu, plo, 1);
    plo += __shfl_xor_sync(0xffffffffu, plo, 2);
    phi += __shfl_xor_sync(0xffffffffu, phi, 1);
    phi += __shfl_xor_sync(0xffffffffu, phi, 2);
    if ((lane & 3) == 0) {
        int r0 = wid * 16 + (lane >> 2);
        int p0 = pix0 + r0;
        int p1 = p0 + 8;
        int b0 = p0 >> 10, b1 = p1 >> 10;
        g_logits[(b0 * 8 + head) * 1024 + (p0 & 1023)] = plo;
        g_logits[(b1 * 8 + head) * 1024 + (p1 & 1023)] = phi;
    }
}

// ---------------------------------------------------------------- kernel: fused softmax + outer store
__global__ void outer_kernel(float* __restrict__ out) {
    int r = blockIdx.x;        // (b*8+n)*32 + h
    int bn = r >> 5;
    int h = r & 31;
    __shared__ float4 vs[256];
    __shared__ float ws[32];
    vs[threadIdx.x] = ((const float4*)(g_vsum + bn * 1024))[threadIdx.x];
    if (threadIdx.x < 32) {
        int lane = threadIdx.x;
        float v = g_logits[bn * 1024 + h * 32 + lane] * 0.125f;
        float m = v;
#pragma unroll
        for (int o = 16; o > 0; o >>= 1) m = fmaxf(m, __shfl_xor_sync(0xffffffffu, m, o));
        float e = __expf(v - m);
        float s = e;
#pragma unroll
        for (int o = 16; o > 0; o >>= 1) s += __shfl_xor_sync(0xffffffffu, s, o);
        ws[lane] = e / s;
    }
    __syncthreads();
    float4 v = vs[threadIdx.x];
    float4* o = (float4*)out + (size_t)r * 8192;
#pragma unroll
    for (int w = 0; w < 32; ++w) {
        float s = ws[w];
        float4 t = make_float4(s * v.x, s * v.y, s * v.z, s * v.w);
        __stcs(&o[w * 256 + threadIdx.x], t);
    }
}

// ----------------------------------------------------------------
extern "C" void kernel_launch(void* const* d_in, const int* in_sizes, int n_in,
                              void* d_out, int out_size) {
    const float* x  = (const float*)d_in[0];
    const float* wq = (const float*)d_in[1];
    const float* wk = (const float*)d_in[2];
    const float* wv = (const float*)d_in[3];
    float* out = (float*)d_out;

    cudaFuncSetAttribute(qk_kernel, cudaFuncAttributeMaxDynamicSharedMemorySize, SM_TOTAL);

    __nv_bfloat16 *xhi, *xlo, *wqhi, *wqlo, *wkhi, *wklo;
    cudaGetSymbolAddress((void**)&xhi, g_xhi);
    cudaGetSymbolAddress((void**)&xlo, g_xlo);
    cudaGetSymbolAddress((void**)&wqhi, g_wqhi);
    cudaGetSymbolAddress((void**)&wqlo, g_wqlo);
    cudaGetSymbolAddress((void**)&wkhi, g_wkhi);
    cudaGetSymbolAddress((void**)&wklo, g_wklo);

    split_kernel<<<4096, 256>>>(x, xhi, xlo, 8192 * 512 / 4);
    split_kernel<<<256, 256>>>(wq, wqhi, wqlo, 512 * 512 / 4);
    split_kernel<<<256, 256>>>(wk, wkhi, wklo, 512 * 512 / 4);
    wvsum_kernel<<<8, 512>>>(wv);
    vsum_kernel<<<1024, 256>>>(x);
    qk_kernel<<<dim3(64, 8), 256, SM_TOTAL>>>();
    outer_kernel<<<2048, 256>>>(out);
}

// round 6
// speedup vs baseline: 1.1980x; 1.1980x over previous
#include <cuda_runtime.h>
#include <cuda_fp16.h>
#include <stdint.h>
#include <math.h>

// ---------------------------------------------------------------- scratch
__device__ float g_logits[8 * 8 * 32 * 32];   // [b][n][h][w] raw logits
__device__ float g_vsum[8 * 8 * 32 * 32];     // [b][n][x][y]
__device__ float g_wvsum[8 * 512];
__device__ __half g_xhi[8192 * 512];
__device__ __half g_xlo[8192 * 512];
__device__ __half g_wqh[512 * 512];
__device__ __half g_wkh[512 * 512];

// ---------------------------------------------------------------- helpers
__device__ __forceinline__ uint32_t smem_u32(const void* p) {
    uint32_t a;
    asm("{ .reg .u64 t; cvta.to.shared.u64 t, %1; cvt.u32.u64 %0, t; }" : "=r"(a) : "l"(p));
    return a;
}
__device__ __forceinline__ void ldsm4(uint32_t* r, uint32_t addr) {
    asm volatile("ldmatrix.sync.aligned.m8n8.x4.shared.b16 {%0,%1,%2,%3}, [%4];"
                 : "=r"(r[0]), "=r"(r[1]), "=r"(r[2]), "=r"(r[3]) : "r"(addr));
}
__device__ __forceinline__ void mma16816(float* d, const uint32_t* a, const uint32_t* b) {
    asm volatile(
        "mma.sync.aligned.m16n8k16.row.col.f32.f16.f16.f32 "
        "{%0,%1,%2,%3}, {%4,%5,%6,%7}, {%8,%9}, {%0,%1,%2,%3};"
        : "+f"(d[0]), "+f"(d[1]), "+f"(d[2]), "+f"(d[3])
        : "r"(a[0]), "r"(a[1]), "r"(a[2]), "r"(a[3]), "r"(b[0]), "r"(b[1]));
}
__device__ __forceinline__ void cp_async16(uint32_t dst, const void* src) {
    asm volatile("cp.async.cg.shared.global [%0], [%1], 16;"
                 :: "r"(dst), "l"(__cvta_generic_to_global(src)) : "memory");
}
__device__ __forceinline__ void cp_commit_wait() {
    asm volatile("cp.async.commit_group;\ncp.async.wait_group 0;" ::: "memory");
}

// ---------------------------------------------------------------- kernel: x hi/lo fp16 split
__global__ void split2_kernel(const float* __restrict__ src,
                              __half* __restrict__ hi,
                              __half* __restrict__ lo, int n4) {
    int i = blockIdx.x * blockDim.x + threadIdx.x;
    if (i >= n4) return;
    float4 v = ((const float4*)src)[i];
    __half h0 = __float2half(v.x), h1 = __float2half(v.y);
    __half h2 = __float2half(v.z), h3 = __float2half(v.w);
    __half l0 = __float2half(v.x - __half2float(h0));
    __half l1 = __float2half(v.y - __half2float(h1));
    __half l2 = __float2half(v.z - __half2float(h2));
    __half l3 = __float2half(v.w - __half2float(h3));
    ((ushort4*)hi)[i] = make_ushort4(__half_as_ushort(h0), __half_as_ushort(h1),
                                     __half_as_ushort(h2), __half_as_ushort(h3));
    ((ushort4*)lo)[i] = make_ushort4(__half_as_ushort(l0), __half_as_ushort(l1),
                                     __half_as_ushort(l2), __half_as_ushort(l3));
}

// ---------------------------------------------------------------- kernel: w -> fp16 (single)
__global__ void cvt_kernel(const float* __restrict__ src, __half* __restrict__ dst, int n4) {
    int i = blockIdx.x * blockDim.x + threadIdx.x;
    if (i >= n4) return;
    float4 v = ((const float4*)src)[i];
    ((ushort4*)dst)[i] = make_ushort4(
        __half_as_ushort(__float2half(v.x)), __half_as_ushort(__float2half(v.y)),
        __half_as_ushort(__float2half(v.z)), __half_as_ushort(__float2half(v.w)));
}

// ---------------------------------------------------------------- kernel: wvsum (parallel)
// 32 blocks: (head n, col chunk of 128). 128 threads, one col each, sum 64 rows.
__global__ void wvsum_kernel(const float* __restrict__ wv) {
    int n = blockIdx.x >> 2;
    int c = (blockIdx.x & 3) * 128 + threadIdx.x;
    const float* base = wv + (size_t)(n * 64) * 512 + c;
    float s = 0.f;
#pragma unroll 16
    for (int d = 0; d < 64; ++d) s += base[d * 512];
    g_wvsum[n * 512 + c] = s;
}

// ---------------------------------------------------------------- kernel: vsum (fp32)
__global__ void vsum_kernel(const float* __restrict__ x) {
    int p = blockIdx.x * 8 + (threadIdx.x >> 5);
    int lane = threadIdx.x & 31;
    const float4* xr = (const float4*)(x + (size_t)p * 512);
    float4 xv[4];
#pragma unroll
    for (int t = 0; t < 4; ++t) xv[t] = xr[lane * 4 + t];
    float acc[8];
#pragma unroll
    for (int n = 0; n < 8; ++n) {
        const float4* wr = (const float4*)(g_wvsum + n * 512);
        float s = 0.f;
#pragma unroll
        for (int t = 0; t < 4; ++t) {
            float4 w = wr[lane * 4 + t];
            s = fmaf(xv[t].x, w.x, s); s = fmaf(xv[t].y, w.y, s);
            s = fmaf(xv[t].z, w.z, s); s = fmaf(xv[t].w, w.w, s);
        }
#pragma unroll
        for (int o = 16; o > 0; o >>= 1) s += __shfl_xor_sync(0xffffffffu, s, o);
        acc[n] = s;
    }
    if (lane < 8) {
        float v = acc[0];
#pragma unroll
        for (int n = 1; n < 8; ++n) if (lane == n) v = acc[n];
        int b = p >> 10, pos = p & 1023;
        g_vsum[(b * 8 + lane) * 1024 + pos] = v;
    }
}

// ---------------------------------------------------------------- kernel: QK via mma.sync, 2-pass fp16
// block = (128-pixel tile) x (head). 256 threads / 8 warps, 16 rows per warp.
// smem fp16 tiles, row stride 144 B for conflict-free ldmatrix.
static constexpr int RS   = 144;
static constexpr int XH_O = 0;              // X hi (128 x 72)
static constexpr int XL_O = 18432;          // X lo
static constexpr int QH_O = 36864;          // Wq  (64 x 72)
static constexpr int KH_O = 46080;          // Wk
static constexpr int SM_TOTAL = 55296;

__global__ void __launch_bounds__(256, 2)
qk_kernel() {
    extern __shared__ char smem[];
    const uint32_t sb = smem_u32(smem);
    const int tid  = threadIdx.x;
    const int lane = tid & 31;
    const int wid  = tid >> 5;
    const int tile = blockIdx.x;      // 0..63
    const int head = blockIdx.y;      // 0..7
    const int pix0 = tile * 128;

    const uint32_t a_off = sb + (uint32_t)(wid * 16 + (lane & 15)) * RS + ((lane >> 4) << 4);
    const uint32_t b_row = (lane & 7) + ((lane >> 4) << 3);
    const uint32_t b_off = sb + b_row * RS + (((lane >> 3) & 1) << 4);

    float accQ[8][4], accK[8][4];
#pragma unroll
    for (int i = 0; i < 8; ++i)
#pragma unroll
        for (int j = 0; j < 4; ++j) { accQ[i][j] = 0.f; accK[i][j] = 0.f; }

    const int c8 = tid & 7;                   // 16B chunk within a 64-col row
    for (int ch = 0; ch < 8; ++ch) {
        const int c0 = ch * 64;
        // X hi+lo: 128 rows x 8 chunks each; 1024 idx per array, 4 iters
#pragma unroll
        for (int g = 0; g < 4; ++g) {
            int idx = tid + g * 256;          // 0..1023
            int r = idx >> 3, cc = idx & 7;
            uint32_t so = (uint32_t)r * RS + cc * 16;
            const size_t gg = (size_t)(pix0 + r) * 512 + c0 + cc * 8;
            cp_async16(sb + XH_O + so, g_xhi + gg);
            cp_async16(sb + XL_O + so, g_xlo + gg);
        }
        // W q/k: 64 rows x 8 chunks each; 512 idx per array, 2 iters
#pragma unroll
        for (int g = 0; g < 2; ++g) {
            int idx = tid + g * 256;          // 0..511
            int r = idx >> 3, cc = idx & 7;
            uint32_t so = (uint32_t)r * RS + cc * 16;
            const size_t gg = (size_t)(head * 64 + r) * 512 + c0 + cc * 8;
            cp_async16(sb + QH_O + so, g_wqh + gg);
            cp_async16(sb + KH_O + so, g_wkh + gg);
        }
        cp_commit_wait();
        __syncthreads();

#pragma unroll
        for (int ks = 0; ks < 4; ++ks) {
            const uint32_t ko = ks * 32;
            uint32_t ah[4], al[4];
            ldsm4(ah, a_off + XH_O + ko);
            ldsm4(al, a_off + XL_O + ko);
#pragma unroll
            for (int np = 0; np < 4; ++np) {
                const uint32_t off = b_off + np * (16 * RS) + ko;
                uint32_t bq[4], bk[4];
                ldsm4(bq, off + QH_O);
                ldsm4(bk, off + KH_O);
                mma16816(accQ[np * 2],     ah, bq);
                mma16816(accQ[np * 2],     al, bq);
                mma16816(accQ[np * 2 + 1], ah, bq + 2);
                mma16816(accQ[np * 2 + 1], al, bq + 2);
                mma16816(accK[np * 2],     ah, bk);
                mma16816(accK[np * 2],     al, bk);
                mma16816(accK[np * 2 + 1], ah, bk + 2);
                mma16816(accK[np * 2 + 1], al, bk + 2);
            }
        }
        __syncthreads();
        (void)c8;
    }

    // epilogue: per-pixel dot over the 64 j's
    float plo = 0.f, phi = 0.f;
#pragma unroll
    for (int nt = 0; nt < 8; ++nt) {
        plo = fmaf(accQ[nt][0], accK[nt][0], plo);
        plo = fmaf(accQ[nt][1], accK[nt][1], plo);
        phi = fmaf(accQ[nt][2], accK[nt][2], phi);
        phi = fmaf(accQ[nt][3], accK[nt][3], phi);
    }
    plo += __shfl_xor_sync(0xffffffffu, plo, 1);
    plo += __shfl_xor_sync(0xffffffffu, plo, 2);
    phi += __shfl_xor_sync(0xffffffffu, phi, 1);
    phi += __shfl_xor_sync(0xffffffffu, phi, 2);
    if ((lane & 3) == 0) {
        int r0 = wid * 16 + (lane >> 2);
        int p0 = pix0 + r0;
        int p1 = p0 + 8;
        int b0 = p0 >> 10, b1 = p1 >> 10;
        g_logits[(b0 * 8 + head) * 1024 + (p0 & 1023)] = plo;
        g_logits[(b1 * 8 + head) * 1024 + (p1 & 1023)] = phi;
    }
}

// ---------------------------------------------------------------- kernel: fused softmax + outer store
__global__ void outer_kernel(float* __restrict__ out) {
    int r = blockIdx.x;        // (b*8+n)*32 + h
    int bn = r >> 5;
    int h = r & 31;
    __shared__ float4 vs[256];
    __shared__ float ws[32];
    vs[threadIdx.x] = ((const float4*)(g_vsum + bn * 1024))[threadIdx.x];
    if (threadIdx.x < 32) {
        int lane = threadIdx.x;
        float v = g_logits[bn * 1024 + h * 32 + lane] * 0.125f;
        float m = v;
#pragma unroll
        for (int o = 16; o > 0; o >>= 1) m = fmaxf(m, __shfl_xor_sync(0xffffffffu, m, o));
        float e = __expf(v - m);
        float s = e;
#pragma unroll
        for (int o = 16; o > 0; o >>= 1) s += __shfl_xor_sync(0xffffffffu, s, o);
        ws[lane] = e / s;
    }
    __syncthreads();
    float4 v = vs[threadIdx.x];
    float4* o = (float4*)out + (size_t)r * 8192;
#pragma unroll
    for (int w = 0; w < 32; ++w) {
        float s = ws[w];
        float4 t = make_float4(s * v.x, s * v.y, s * v.z, s * v.w);
        __stcs(&o[w * 256 + threadIdx.x], t);
    }
}

// ----------------------------------------------------------------
extern "C" void kernel_launch(void* const* d_in, const int* in_sizes, int n_in,
                              void* d_out, int out_size) {
    const float* x  = (const float*)d_in[0];
    const float* wq = (const float*)d_in[1];
    const float* wk = (const float*)d_in[2];
    const float* wv = (const float*)d_in[3];
    float* out = (float*)d_out;

    cudaFuncSetAttribute(qk_kernel, cudaFuncAttributeMaxDynamicSharedMemorySize, SM_TOTAL);

    __half *xhi, *xlo, *wqh, *wkh;
    cudaGetSymbolAddress((void**)&xhi, g_xhi);
    cudaGetSymbolAddress((void**)&xlo, g_xlo);
    cudaGetSymbolAddress((void**)&wqh, g_wqh);
    cudaGetSymbolAddress((void**)&wkh, g_wkh);

    split2_kernel<<<4096, 256>>>(x, xhi, xlo, 8192 * 512 / 4);
    cvt_kernel<<<256, 256>>>(wq, wqh, 512 * 512 / 4);
    cvt_kernel<<<256, 256>>>(wk, wkh, 512 * 512 / 4);
    wvsum_kernel<<<32, 128>>>(wv);
    vsum_kernel<<<1024, 256>>>(x);
    qk_kernel<<<dim3(64, 8), 256, SM_TOTAL>>>();
    outer_kernel<<<2048, 256>>>(out);
}